// round 2
// baseline (speedup 1.0000x reference)
#include <cuda_runtime.h>
#include <cuda_bf16.h>
#include <math.h>

// ---------------------------------------------------------------------------
// DDiT block, fp32 baseline.
// T=8192 tokens, DIM=1024, 16 heads x 64, B=8 seqs of L=1024, MLP hidden 4096.
// ---------------------------------------------------------------------------

#define T_TOK   8192
#define DIM     1024
#define NH      16
#define HD      64
#define NSEQ    8
#define SEQL    1024
#define HIDDEN  4096
#define ADA_N   6144

// scratch (allocation-free rule: __device__ globals)
__device__ float g_ada [NSEQ * ADA_N];
__device__ float g_h   [T_TOK * DIM];
__device__ float g_q   [T_TOK * DIM];
__device__ float g_k   [T_TOK * DIM];
__device__ float g_v   [T_TOK * DIM];
__device__ float g_attn[T_TOK * DIM];
__device__ float g_mid [T_TOK * HIDDEN];

// ---------------------------------------------------------------------------
// 1) ada = c @ ada_w + ada_b     [8,1024] x [1024,6144]
// ---------------------------------------------------------------------------
__global__ void ada_kernel(const float* __restrict__ c,
                           const float* __restrict__ W,
                           const float* __restrict__ b,
                           float* __restrict__ out)
{
    __shared__ float cs[NSEQ * 1024];
    int tid = threadIdx.x; // 128
    for (int i = tid; i < NSEQ * 1024; i += 128) cs[i] = c[i];
    __syncthreads();
    int n = blockIdx.x * 128 + tid;
    float acc[NSEQ];
#pragma unroll
    for (int r = 0; r < NSEQ; r++) acc[r] = 0.f;
    for (int k = 0; k < 1024; k++) {
        float wv = W[(size_t)k * ADA_N + n];
#pragma unroll
        for (int r = 0; r < NSEQ; r++) acc[r] = fmaf(cs[r * 1024 + k], wv, acc[r]);
    }
    float bv = b[n];
#pragma unroll
    for (int r = 0; r < NSEQ; r++) out[r * ADA_N + n] = acc[r] + bv;
}

// ---------------------------------------------------------------------------
// 2) LayerNorm (weight only) + adaLN modulate:
//    out = norm(x)*w*(1+sc) + sh,  sc/sh per (seq, channel)
// ---------------------------------------------------------------------------
__global__ void ln_mod_kernel(const float* __restrict__ x,
                              const float* __restrict__ w,
                              const float* __restrict__ ada,
                              int sh_off, int sc_off,
                              float* __restrict__ out)
{
    int row = blockIdx.x;
    int tid = threadIdx.x; // 256
    const float* xr = x + (size_t)row * DIM;
    float4 v = *(const float4*)(xr + tid * 4);
    float s  = v.x + v.y + v.z + v.w;
    float ss = fmaf(v.x, v.x, fmaf(v.y, v.y, fmaf(v.z, v.z, v.w * v.w)));
#pragma unroll
    for (int o = 16; o; o >>= 1) {
        s  += __shfl_xor_sync(0xffffffffu, s,  o);
        ss += __shfl_xor_sync(0xffffffffu, ss, o);
    }
    __shared__ float sm1[8], sm2[8];
    int wid = tid >> 5, lane = tid & 31;
    if (!lane) { sm1[wid] = s; sm2[wid] = ss; }
    __syncthreads();
    float ts = 0.f, tss = 0.f;
#pragma unroll
    for (int i = 0; i < 8; i++) { ts += sm1[i]; tss += sm2[i]; }
    float mu   = ts * (1.f / DIM);
    float var  = tss * (1.f / DIM) - mu * mu;
    float rstd = rsqrtf(var + 1e-5f);
    int sq = row >> 10;  // equal lengths: seq id = token/1024
    const float* ar = ada + (size_t)sq * ADA_N;
    int c0 = tid * 4;
    float4 o4;
    o4.x = (v.x - mu) * rstd * w[c0 + 0] * (1.f + ar[sc_off + c0 + 0]) + ar[sh_off + c0 + 0];
    o4.y = (v.y - mu) * rstd * w[c0 + 1] * (1.f + ar[sc_off + c0 + 1]) + ar[sh_off + c0 + 1];
    o4.z = (v.z - mu) * rstd * w[c0 + 2] * (1.f + ar[sc_off + c0 + 2]) + ar[sh_off + c0 + 2];
    o4.w = (v.w - mu) * rstd * w[c0 + 3] * (1.f + ar[sc_off + c0 + 3]) + ar[sh_off + c0 + 3];
    *(float4*)(out + (size_t)row * DIM + c0) = o4;
}

// ---------------------------------------------------------------------------
// 3) Generic tiled SGEMM: C = A[M,K] @ B[K,N] with fused epilogues
//    128x128 block tile, 8x8 per thread, Ktile=8, 256 threads
// ---------------------------------------------------------------------------
#define EPI_STORE   0
#define EPI_GELU    1   // C = gelu(acc + bias[n])
#define EPI_ATTNOUT 2   // C = skip + ada[seq][gate_off+n] * acc
#define EPI_MLPOUT  3   // C = skip + ada[seq][gate_off+n] * (acc + bias[n])

__device__ __forceinline__ float gelu_tanh(float x)
{
    float x3 = x * x * x;
    float t  = tanhf(0.7978845608028654f * (x + 0.044715f * x3));
    return 0.5f * x * (1.f + t);
}

template <int EPI>
__global__ void __launch_bounds__(256, 1)
sgemm_kernel(const float* __restrict__ A,
             const float* __restrict__ Bm,
             float* __restrict__ C,
             int M, int N, int K,
             const float* __restrict__ bias,
             const float* __restrict__ skip,
             const float* __restrict__ ada,
             int gate_off)
{
    __shared__ float As[8][132]; // As[k][m] (transposed A tile)
    __shared__ float Bs[8][132];
    int tid = threadIdx.x;
    int m0 = blockIdx.y * 128;
    int n0 = blockIdx.x * 128;
    int ty = tid >> 4, tx = tid & 15;

    float acc[8][8];
#pragma unroll
    for (int i = 0; i < 8; i++)
#pragma unroll
        for (int j = 0; j < 8; j++) acc[i][j] = 0.f;

    int arow = tid >> 1, acol = (tid & 1) * 4;
    int brow = tid >> 5, bcol = (tid & 31) * 4;
    const float* Aptr = A  + (size_t)(m0 + arow) * K + acol;
    const float* Bptr = Bm + (size_t)brow * N + n0 + bcol;

    for (int k0 = 0; k0 < K; k0 += 8) {
        float4 av = *(const float4*)Aptr;
        float4 bv = *(const float4*)Bptr;
        __syncthreads();
        As[acol + 0][arow] = av.x;
        As[acol + 1][arow] = av.y;
        As[acol + 2][arow] = av.z;
        As[acol + 3][arow] = av.w;
        *(float4*)&Bs[brow][bcol] = bv;
        __syncthreads();
#pragma unroll
        for (int kk = 0; kk < 8; kk++) {
            float4 a0 = *(const float4*)&As[kk][ty * 8];
            float4 a1 = *(const float4*)&As[kk][ty * 8 + 4];
            float4 b0 = *(const float4*)&Bs[kk][tx * 8];
            float4 b1 = *(const float4*)&Bs[kk][tx * 8 + 4];
            float af[8] = {a0.x, a0.y, a0.z, a0.w, a1.x, a1.y, a1.z, a1.w};
            float bf[8] = {b0.x, b0.y, b0.z, b0.w, b1.x, b1.y, b1.z, b1.w};
#pragma unroll
            for (int i = 0; i < 8; i++)
#pragma unroll
                for (int j = 0; j < 8; j++)
                    acc[i][j] = fmaf(af[i], bf[j], acc[i][j]);
        }
        Aptr += 8;
        Bptr += (size_t)8 * N;
    }

#pragma unroll
    for (int i = 0; i < 8; i++) {
        int row = m0 + ty * 8 + i;
        int col0 = n0 + tx * 8;
        size_t off = (size_t)row * N + col0;
        int sq = row >> 10;
        float r[8];
#pragma unroll
        for (int j = 0; j < 8; j++) {
            int col = col0 + j;
            float v = acc[i][j];
            if (EPI == EPI_STORE) {
                r[j] = v;
            } else if (EPI == EPI_GELU) {
                r[j] = gelu_tanh(v + bias[col]);
            } else if (EPI == EPI_ATTNOUT) {
                float g = ada[(size_t)sq * ADA_N + gate_off + col];
                r[j] = skip[off + j] + g * v;
            } else { // EPI_MLPOUT
                float g = ada[(size_t)sq * ADA_N + gate_off + col];
                r[j] = skip[off + j] + g * (v + bias[col]);
            }
        }
        *(float4*)(C + off)     = make_float4(r[0], r[1], r[2], r[3]);
        *(float4*)(C + off + 4) = make_float4(r[4], r[5], r[6], r[7]);
    }
}

// ---------------------------------------------------------------------------
// 4) RoPE (half-split), in-place on q and k. pos = token & 1023 (equal lengths)
// ---------------------------------------------------------------------------
__global__ void rope_kernel(float* __restrict__ q, float* __restrict__ k,
                            const float* __restrict__ cosT,
                            const float* __restrict__ sinT)
{
    int idx = blockIdx.x * 256 + threadIdx.x;
    if (idx >= T_TOK * NH * 32) return;
    int i = idx & 31;
    int h = (idx >> 5) & 15;
    int t = idx >> 9;
    int pos = t & (SEQL - 1);
    float c = cosT[pos * 32 + i];
    float s = sinT[pos * 32 + i];
    size_t base = (size_t)t * DIM + h * HD + i;
    float q1 = q[base], q2 = q[base + 32];
    q[base]      = q1 * c - q2 * s;
    q[base + 32] = q2 * c + q1 * s;
    float k1 = k[base], k2 = k[base + 32];
    k[base]      = k1 * c - k2 * s;
    k[base + 32] = k2 * c + k1 * s;
}

// ---------------------------------------------------------------------------
// 5) Flash attention, fp32. One block = (64 q-rows, one (b,h)).
//    Loop over 16 KV tiles of 64. 256 threads as 16x16, 4x4 micro-tiles.
// ---------------------------------------------------------------------------
#define APAD 68  // row stride (words) in smem tiles

__global__ void __launch_bounds__(256, 1)
attn_kernel(const float* __restrict__ q,
            const float* __restrict__ k,
            const float* __restrict__ v,
            float* __restrict__ o)
{
    extern __shared__ float sm[];
    float* QsT = sm;                 // [d][row]  64x68
    float* KsT = sm + 64 * APAD;     // [d][n]
    float* Vs  = sm + 2 * 64 * APAD; // [n][d]
    float* Pt  = sm + 3 * 64 * APAD; // [n][row]

    int bh = blockIdx.y;
    int b = bh >> 4, h = bh & 15;
    int m0 = blockIdx.x * 64;
    int tid = threadIdx.x;
    int ty = tid >> 4, tx = tid & 15;

    const float* qbase = q + ((size_t)(b * SEQL + m0)) * DIM + h * HD;
#pragma unroll
    for (int it = 0; it < 4; it++) {
        int lin = tid + it * 256;
        int r = lin >> 4;
        int d = (lin & 15) * 4;
        float4 qv = *(const float4*)(qbase + (size_t)r * DIM + d);
        QsT[(d + 0) * APAD + r] = qv.x * 0.125f;
        QsT[(d + 1) * APAD + r] = qv.y * 0.125f;
        QsT[(d + 2) * APAD + r] = qv.z * 0.125f;
        QsT[(d + 3) * APAD + r] = qv.w * 0.125f;
    }

    float mi[4], li[4], accO[4][4];
#pragma unroll
    for (int i = 0; i < 4; i++) {
        mi[i] = -1e30f; li[i] = 0.f;
#pragma unroll
        for (int j = 0; j < 4; j++) accO[i][j] = 0.f;
    }

    for (int nt = 0; nt < 16; nt++) {
        const float* kbase = k + ((size_t)(b * SEQL + nt * 64)) * DIM + h * HD;
        const float* vbase = v + ((size_t)(b * SEQL + nt * 64)) * DIM + h * HD;
        __syncthreads(); // previous PV reads done before overwriting K/V
#pragma unroll
        for (int it = 0; it < 4; it++) {
            int lin = tid + it * 256;
            int r = lin >> 4;
            int d = (lin & 15) * 4;
            float4 kv = *(const float4*)(kbase + (size_t)r * DIM + d);
            KsT[(d + 0) * APAD + r] = kv.x;
            KsT[(d + 1) * APAD + r] = kv.y;
            KsT[(d + 2) * APAD + r] = kv.z;
            KsT[(d + 3) * APAD + r] = kv.w;
            float4 vv = *(const float4*)(vbase + (size_t)r * DIM + d);
            *(float4*)&Vs[r * APAD + d] = vv;
        }
        __syncthreads();

        float s4[4][4];
#pragma unroll
        for (int i = 0; i < 4; i++)
#pragma unroll
            for (int j = 0; j < 4; j++) s4[i][j] = 0.f;
#pragma unroll 4
        for (int d = 0; d < 64; d++) {
            float4 a = *(const float4*)&QsT[d * APAD + ty * 4];
            float4 bb = *(const float4*)&KsT[d * APAD + tx * 4];
            float af[4] = {a.x, a.y, a.z, a.w};
            float bf[4] = {bb.x, bb.y, bb.z, bb.w};
#pragma unroll
            for (int i = 0; i < 4; i++)
#pragma unroll
                for (int j = 0; j < 4; j++)
                    s4[i][j] = fmaf(af[i], bf[j], s4[i][j]);
        }

        // online softmax (row reductions across the 16 tx lanes of each half-warp)
#pragma unroll
        for (int i = 0; i < 4; i++) {
            float rm = fmaxf(fmaxf(s4[i][0], s4[i][1]), fmaxf(s4[i][2], s4[i][3]));
#pragma unroll
            for (int off = 8; off; off >>= 1)
                rm = fmaxf(rm, __shfl_xor_sync(0xffffffffu, rm, off));
            float mn = fmaxf(mi[i], rm);
            float al = __expf(mi[i] - mn);
            mi[i] = mn;
            li[i] *= al;
#pragma unroll
            for (int j = 0; j < 4; j++) accO[i][j] *= al;
            float rs = 0.f;
#pragma unroll
            for (int j = 0; j < 4; j++) {
                s4[i][j] = __expf(s4[i][j] - mn);
                rs += s4[i][j];
            }
#pragma unroll
            for (int off = 8; off; off >>= 1)
                rs += __shfl_xor_sync(0xffffffffu, rs, off);
            li[i] += rs;
#pragma unroll
            for (int j = 0; j < 4; j++)
                Pt[(tx * 4 + j) * APAD + ty * 4 + i] = s4[i][j];
        }
        __syncthreads();

#pragma unroll 4
        for (int n = 0; n < 64; n++) {
            float4 a = *(const float4*)&Pt[n * APAD + ty * 4];
            float4 bb = *(const float4*)&Vs[n * APAD + tx * 4];
            float af[4] = {a.x, a.y, a.z, a.w};
            float bf[4] = {bb.x, bb.y, bb.z, bb.w};
#pragma unroll
            for (int i = 0; i < 4; i++)
#pragma unroll
                for (int j = 0; j < 4; j++)
                    accO[i][j] = fmaf(af[i], bf[j], accO[i][j]);
        }
    }

    float* obase = o + ((size_t)(b * SEQL + m0)) * DIM + h * HD;
#pragma unroll
    for (int i = 0; i < 4; i++) {
        float inv = 1.f / li[i];
#pragma unroll
        for (int j = 0; j < 4; j++)
            obase[(size_t)(ty * 4 + i) * DIM + tx * 4 + j] = accO[i][j] * inv;
    }
}

// ---------------------------------------------------------------------------
// host launcher
// ---------------------------------------------------------------------------
extern "C" void kernel_launch(void* const* d_in, const int* in_sizes, int n_in,
                              void* d_out, int out_size)
{
    const float* x     = (const float*)d_in[0];
    // d_in[1] lengths, d_in[2] offsets: equal lengths, unused (seq = t>>10)
    const float* cosT  = (const float*)d_in[3];
    const float* sinT  = (const float*)d_in[4];
    // d_in[5] positions: equal-length layout -> pos = t & 1023, unused
    const float* c     = (const float*)d_in[6];
    const float* ln1_w = (const float*)d_in[7];
    const float* Wq    = (const float*)d_in[8];
    const float* Wk    = (const float*)d_in[9];
    const float* Wv    = (const float*)d_in[10];
    const float* Wo    = (const float*)d_in[11];
    const float* ln2_w = (const float*)d_in[12];
    const float* W1    = (const float*)d_in[13];
    const float* b1    = (const float*)d_in[14];
    const float* W2    = (const float*)d_in[15];
    const float* b2    = (const float*)d_in[16];
    const float* ada_w = (const float*)d_in[17];
    const float* ada_b = (const float*)d_in[18];
    float* out = (float*)d_out;

    static float *p_ada = nullptr, *p_h, *p_q, *p_k, *p_v, *p_attn, *p_mid;
    static bool attr_set = false;
    if (!p_ada) {
        cudaGetSymbolAddress((void**)&p_ada,  g_ada);
        cudaGetSymbolAddress((void**)&p_h,    g_h);
        cudaGetSymbolAddress((void**)&p_q,    g_q);
        cudaGetSymbolAddress((void**)&p_k,    g_k);
        cudaGetSymbolAddress((void**)&p_v,    g_v);
        cudaGetSymbolAddress((void**)&p_attn, g_attn);
        cudaGetSymbolAddress((void**)&p_mid,  g_mid);
    }

    // 1) adaLN projection
    ada_kernel<<<ADA_N / 128, 128>>>(c, ada_w, ada_b, p_ada);

    // 2) LN1 + modulate (sh_msa @0, sc_msa @1024)
    ln_mod_kernel<<<T_TOK, 256>>>(x, ln1_w, p_ada, 0, 1024, p_h);

    // 3) QKV projections
    dim3 g1(DIM / 128, T_TOK / 128);
    sgemm_kernel<EPI_STORE><<<g1, 256>>>(p_h, Wq, p_q, T_TOK, DIM, DIM, nullptr, nullptr, nullptr, 0);
    sgemm_kernel<EPI_STORE><<<g1, 256>>>(p_h, Wk, p_k, T_TOK, DIM, DIM, nullptr, nullptr, nullptr, 0);
    sgemm_kernel<EPI_STORE><<<g1, 256>>>(p_h, Wv, p_v, T_TOK, DIM, DIM, nullptr, nullptr, nullptr, 0);

    // 4) RoPE
    rope_kernel<<<(T_TOK * NH * 32 + 255) / 256, 256>>>(p_q, p_k, cosT, sinT);

    // 5) attention
    int smem_bytes = 4 * 64 * APAD * sizeof(float); // 69632
    if (!attr_set) {
        cudaFuncSetAttribute(attn_kernel, cudaFuncAttributeMaxDynamicSharedMemorySize, smem_bytes);
        attr_set = true;
    }
    attn_kernel<<<dim3(SEQL / 64, NSEQ * NH), 256, smem_bytes>>>(p_q, p_k, p_v, p_attn);

    // 6) x1 = x + g_msa * (attn @ Wo)   -> written to d_out (gate g_msa @2048)
    sgemm_kernel<EPI_ATTNOUT><<<g1, 256>>>(p_attn, Wo, out, T_TOK, DIM, DIM, nullptr, x, p_ada, 2048);

    // 7) LN2 + modulate (sh_mlp @3072, sc_mlp @4096)
    ln_mod_kernel<<<T_TOK, 256>>>(out, ln2_w, p_ada, 3072, 4096, p_h);

    // 8) mid = gelu(h2 @ W1 + b1)
    dim3 g2(HIDDEN / 128, T_TOK / 128);
    sgemm_kernel<EPI_GELU><<<g2, 256>>>(p_h, W1, p_mid, T_TOK, HIDDEN, DIM, b1, nullptr, nullptr, 0);

    // 9) out = x1 + g_mlp * (mid @ W2 + b2)   (gate g_mlp @5120)
    sgemm_kernel<EPI_MLPOUT><<<g1, 256>>>(p_mid, W2, out, T_TOK, DIM, HIDDEN, b2, out, p_ada, 5120);
}

// round 14
// speedup vs baseline: 2.4587x; 2.4587x over previous
#include <cuda_runtime.h>
#include <cuda_bf16.h>
#include <math.h>
#include <stdint.h>

// ---------------------------------------------------------------------------
// DDiT block. GEMMs on tensor cores (mma.sync tf32), attention fp32 SIMT.
// T=8192 tokens, DIM=1024, 16 heads x 64, B=8 seqs of L=1024, MLP hidden 4096.
// ---------------------------------------------------------------------------

#define T_TOK   8192
#define DIM     1024
#define NH      16
#define HD      64
#define NSEQ    8
#define SEQL    1024
#define HIDDEN  4096
#define ADA_N   6144

// scratch (allocation-free rule: __device__ globals)
__device__ float g_ada [NSEQ * ADA_N];
__device__ float g_h   [T_TOK * DIM];
__device__ float g_q   [T_TOK * DIM];
__device__ float g_k   [T_TOK * DIM];
__device__ float g_v   [T_TOK * DIM];
__device__ float g_attn[T_TOK * DIM];
__device__ float g_mid [T_TOK * HIDDEN];

// ---------------------------------------------------------------------------
// tf32 helpers
// ---------------------------------------------------------------------------
__device__ __forceinline__ uint32_t f2tf32(float x)
{
    uint32_t r;
    asm("cvt.rna.tf32.f32 %0, %1;" : "=r"(r) : "f"(x));
    return r;
}

__device__ __forceinline__ void mma_tf32(float* d, const uint32_t* a, const uint32_t* b)
{
    asm volatile(
        "mma.sync.aligned.m16n8k8.row.col.f32.tf32.tf32.f32 "
        "{%0,%1,%2,%3},{%4,%5,%6,%7},{%8,%9},{%0,%1,%2,%3};"
        : "+f"(d[0]), "+f"(d[1]), "+f"(d[2]), "+f"(d[3])
        : "r"(a[0]), "r"(a[1]), "r"(a[2]), "r"(a[3]),
          "r"(b[0]), "r"(b[1]));
}

// ---------------------------------------------------------------------------
// 1) ada = c @ ada_w + ada_b     [8,1024] x [1024,6144]  (tiny, FFMA fine)
// ---------------------------------------------------------------------------
__global__ void ada_kernel(const float* __restrict__ c,
                           const float* __restrict__ W,
                           const float* __restrict__ b,
                           float* __restrict__ out)
{
    __shared__ float cs[NSEQ * 1024];
    int tid = threadIdx.x; // 128
    for (int i = tid; i < NSEQ * 1024; i += 128) cs[i] = c[i];
    __syncthreads();
    int n = blockIdx.x * 128 + tid;
    float acc[NSEQ];
#pragma unroll
    for (int r = 0; r < NSEQ; r++) acc[r] = 0.f;
    for (int k = 0; k < 1024; k++) {
        float wv = W[(size_t)k * ADA_N + n];
#pragma unroll
        for (int r = 0; r < NSEQ; r++) acc[r] = fmaf(cs[r * 1024 + k], wv, acc[r]);
    }
    float bv = b[n];
#pragma unroll
    for (int r = 0; r < NSEQ; r++) out[r * ADA_N + n] = acc[r] + bv;
}

// ---------------------------------------------------------------------------
// 2) LayerNorm (weight only) + adaLN modulate
// ---------------------------------------------------------------------------
__global__ void ln_mod_kernel(const float* __restrict__ x,
                              const float* __restrict__ w,
                              const float* __restrict__ ada,
                              int sh_off, int sc_off,
                              float* __restrict__ out)
{
    int row = blockIdx.x;
    int tid = threadIdx.x; // 256
    const float* xr = x + (size_t)row * DIM;
    float4 v = *(const float4*)(xr + tid * 4);
    float s  = v.x + v.y + v.z + v.w;
    float ss = fmaf(v.x, v.x, fmaf(v.y, v.y, fmaf(v.z, v.z, v.w * v.w)));
#pragma unroll
    for (int o = 16; o; o >>= 1) {
        s  += __shfl_xor_sync(0xffffffffu, s,  o);
        ss += __shfl_xor_sync(0xffffffffu, ss, o);
    }
    __shared__ float sm1[8], sm2[8];
    int wid = tid >> 5, lane = tid & 31;
    if (!lane) { sm1[wid] = s; sm2[wid] = ss; }
    __syncthreads();
    float ts = 0.f, tss = 0.f;
#pragma unroll
    for (int i = 0; i < 8; i++) { ts += sm1[i]; tss += sm2[i]; }
    float mu   = ts * (1.f / DIM);
    float var  = tss * (1.f / DIM) - mu * mu;
    float rstd = rsqrtf(var + 1e-5f);
    int sq = row >> 10;
    const float* ar = ada + (size_t)sq * ADA_N;
    int c0 = tid * 4;
    float4 o4;
    o4.x = (v.x - mu) * rstd * w[c0 + 0] * (1.f + ar[sc_off + c0 + 0]) + ar[sh_off + c0 + 0];
    o4.y = (v.y - mu) * rstd * w[c0 + 1] * (1.f + ar[sc_off + c0 + 1]) + ar[sh_off + c0 + 1];
    o4.z = (v.z - mu) * rstd * w[c0 + 2] * (1.f + ar[sc_off + c0 + 2]) + ar[sh_off + c0 + 2];
    o4.w = (v.w - mu) * rstd * w[c0 + 3] * (1.f + ar[sc_off + c0 + 3]) + ar[sh_off + c0 + 3];
    *(float4*)(out + (size_t)row * DIM + c0) = o4;
}

// ---------------------------------------------------------------------------
// 3) tf32 tensor-core GEMM: C = A[M,K] @ B[K,N] with fused epilogues
//    128x128 block tile, BK=16, 8 warps (2x4), warp tile 64x32,
//    mma.sync m16n8k8. SMEM k-major, stride 136 (conflict-free frag loads).
// ---------------------------------------------------------------------------
#define EPI_STORE   0
#define EPI_GELU    1   // C = gelu(acc + bias[n])
#define EPI_ATTNOUT 2   // C = skip + ada[seq][gate_off+n] * acc
#define EPI_MLPOUT  3   // C = skip + ada[seq][gate_off+n] * (acc + bias[n])

__device__ __forceinline__ float gelu_tanh(float x)
{
    float x3 = x * x * x;
    float t  = tanhf(0.7978845608028654f * (x + 0.044715f * x3));
    return 0.5f * x * (1.f + t);
}

#define KSTR 136  // smem k-row stride in words: k-stride % 32 == 8 -> no LDS conflicts

template <int EPI>
__global__ void __launch_bounds__(256, 2)
gemm_tc_kernel(const float* __restrict__ A,
               const float* __restrict__ Bm,
               float* __restrict__ C,
               int M, int N, int K,
               const float* __restrict__ bias,
               const float* __restrict__ skip,
               const float* __restrict__ ada,
               int gate_off)
{
    __shared__ uint32_t As[16 * KSTR];  // As[k][m]
    __shared__ uint32_t Bs[16 * KSTR];  // Bs[k][n]

    int tid  = threadIdx.x;
    int m0   = blockIdx.y * 128;
    int n0   = blockIdx.x * 128;
    int warp = tid >> 5;
    int lane = tid & 31;
    int gid  = lane >> 2;   // 0..7
    int tid4 = lane & 3;    // 0..3
    int wm   = warp >> 2;   // 0..1 -> 64 rows
    int wn   = warp & 3;    // 0..3 -> 32 cols

    float d[4][4][4];
#pragma unroll
    for (int mi = 0; mi < 4; mi++)
#pragma unroll
        for (int ni = 0; ni < 4; ni++)
#pragma unroll
            for (int r = 0; r < 4; r++) d[mi][ni][r] = 0.f;

    // global load mapping
    int arow = tid >> 1;            // 0..127
    int acol = (tid & 1) * 8;       // 0 or 8
    int brow = tid >> 4;            // 0..15
    int bcol = (tid & 15) * 8;      // 0..120
    const float* Ap = A  + (size_t)(m0 + arow) * K + acol;
    const float* Bp = Bm + (size_t)brow * N + n0 + bcol;

    for (int k0 = 0; k0 < K; k0 += 16) {
        float4 a0 = ((const float4*)Ap)[0];
        float4 a1 = ((const float4*)Ap)[1];
        float4 b0 = ((const float4*)Bp)[0];
        float4 b1 = ((const float4*)Bp)[1];
        __syncthreads();
        // A: store transposed with tf32 convert
        As[(acol + 0) * KSTR + arow] = f2tf32(a0.x);
        As[(acol + 1) * KSTR + arow] = f2tf32(a0.y);
        As[(acol + 2) * KSTR + arow] = f2tf32(a0.z);
        As[(acol + 3) * KSTR + arow] = f2tf32(a0.w);
        As[(acol + 4) * KSTR + arow] = f2tf32(a1.x);
        As[(acol + 5) * KSTR + arow] = f2tf32(a1.y);
        As[(acol + 6) * KSTR + arow] = f2tf32(a1.z);
        As[(acol + 7) * KSTR + arow] = f2tf32(a1.w);
        // B: row-major store with tf32 convert (vectorized)
        {
            uint4 u0 = make_uint4(f2tf32(b0.x), f2tf32(b0.y), f2tf32(b0.z), f2tf32(b0.w));
            uint4 u1 = make_uint4(f2tf32(b1.x), f2tf32(b1.y), f2tf32(b1.z), f2tf32(b1.w));
            *(uint4*)&Bs[brow * KSTR + bcol]     = u0;
            *(uint4*)&Bs[brow * KSTR + bcol + 4] = u1;
        }
        __syncthreads();

#pragma unroll
        for (int ks = 0; ks < 2; ks++) {
            int kb = ks * 8;
            uint32_t af[4][4];
            uint32_t bf[4][2];
#pragma unroll
            for (int mi = 0; mi < 4; mi++) {
                int m = wm * 64 + mi * 16 + gid;
                af[mi][0] = As[(kb + tid4)     * KSTR + m];
                af[mi][1] = As[(kb + tid4)     * KSTR + m + 8];
                af[mi][2] = As[(kb + tid4 + 4) * KSTR + m];
                af[mi][3] = As[(kb + tid4 + 4) * KSTR + m + 8];
            }
#pragma unroll
            for (int ni = 0; ni < 4; ni++) {
                int n = wn * 32 + ni * 8 + gid;
                bf[ni][0] = Bs[(kb + tid4)     * KSTR + n];
                bf[ni][1] = Bs[(kb + tid4 + 4) * KSTR + n];
            }
#pragma unroll
            for (int mi = 0; mi < 4; mi++)
#pragma unroll
                for (int ni = 0; ni < 4; ni++)
                    mma_tf32(d[mi][ni], af[mi], bf[ni]);
        }
        Ap += 16;
        Bp += (size_t)16 * N;
    }

    // epilogue
#pragma unroll
    for (int mi = 0; mi < 4; mi++) {
        int r0 = m0 + wm * 64 + mi * 16 + gid;
#pragma unroll
        for (int half = 0; half < 2; half++) {
            int row = r0 + half * 8;
            int sq  = row >> 10;
            size_t rowoff = (size_t)row * N;
#pragma unroll
            for (int ni = 0; ni < 4; ni++) {
                int col = n0 + wn * 32 + ni * 8 + 2 * tid4;
                float v0 = d[mi][ni][half * 2 + 0];
                float v1 = d[mi][ni][half * 2 + 1];
                float o0, o1;
                if (EPI == EPI_STORE) {
                    o0 = v0; o1 = v1;
                } else if (EPI == EPI_GELU) {
                    o0 = gelu_tanh(v0 + bias[col]);
                    o1 = gelu_tanh(v1 + bias[col + 1]);
                } else if (EPI == EPI_ATTNOUT) {
                    float g0 = ada[(size_t)sq * ADA_N + gate_off + col];
                    float g1 = ada[(size_t)sq * ADA_N + gate_off + col + 1];
                    float2 sk = *(const float2*)(skip + rowoff + col);
                    o0 = sk.x + g0 * v0;
                    o1 = sk.y + g1 * v1;
                } else { // EPI_MLPOUT
                    float g0 = ada[(size_t)sq * ADA_N + gate_off + col];
                    float g1 = ada[(size_t)sq * ADA_N + gate_off + col + 1];
                    float2 sk = *(const float2*)(skip + rowoff + col);
                    o0 = sk.x + g0 * (v0 + bias[col]);
                    o1 = sk.y + g1 * (v1 + bias[col + 1]);
                }
                *(float2*)(C + rowoff + col) = make_float2(o0, o1);
            }
        }
    }
}

// ---------------------------------------------------------------------------
// 4) RoPE (half-split), in-place on q and k. pos = token & 1023
// ---------------------------------------------------------------------------
__global__ void rope_kernel(float* __restrict__ q, float* __restrict__ k,
                            const float* __restrict__ cosT,
                            const float* __restrict__ sinT)
{
    int idx = blockIdx.x * 256 + threadIdx.x;
    if (idx >= T_TOK * NH * 32) return;
    int i = idx & 31;
    int h = (idx >> 5) & 15;
    int t = idx >> 9;
    int pos = t & (SEQL - 1);
    float c = cosT[pos * 32 + i];
    float s = sinT[pos * 32 + i];
    size_t base = (size_t)t * DIM + h * HD + i;
    float q1 = q[base], q2 = q[base + 32];
    q[base]      = q1 * c - q2 * s;
    q[base + 32] = q2 * c + q1 * s;
    float k1 = k[base], k2 = k[base + 32];
    k[base]      = k1 * c - k2 * s;
    k[base + 32] = k2 * c + k1 * s;
}

// ---------------------------------------------------------------------------
// 5) Flash attention, fp32 SIMT (unchanged this round)
// ---------------------------------------------------------------------------
#define APAD 68

__global__ void __launch_bounds__(256, 1)
attn_kernel(const float* __restrict__ q,
            const float* __restrict__ k,
            const float* __restrict__ v,
            float* __restrict__ o)
{
    extern __shared__ float sm[];
    float* QsT = sm;
    float* KsT = sm + 64 * APAD;
    float* Vs  = sm + 2 * 64 * APAD;
    float* Pt  = sm + 3 * 64 * APAD;

    int bh = blockIdx.y;
    int b = bh >> 4, h = bh & 15;
    int m0 = blockIdx.x * 64;
    int tid = threadIdx.x;
    int ty = tid >> 4, tx = tid & 15;

    const float* qbase = q + ((size_t)(b * SEQL + m0)) * DIM + h * HD;
#pragma unroll
    for (int it = 0; it < 4; it++) {
        int lin = tid + it * 256;
        int r = lin >> 4;
        int d = (lin & 15) * 4;
        float4 qv = *(const float4*)(qbase + (size_t)r * DIM + d);
        QsT[(d + 0) * APAD + r] = qv.x * 0.125f;
        QsT[(d + 1) * APAD + r] = qv.y * 0.125f;
        QsT[(d + 2) * APAD + r] = qv.z * 0.125f;
        QsT[(d + 3) * APAD + r] = qv.w * 0.125f;
    }

    float mi[4], li[4], accO[4][4];
#pragma unroll
    for (int i = 0; i < 4; i++) {
        mi[i] = -1e30f; li[i] = 0.f;
#pragma unroll
        for (int j = 0; j < 4; j++) accO[i][j] = 0.f;
    }

    for (int nt = 0; nt < 16; nt++) {
        const float* kbase = k + ((size_t)(b * SEQL + nt * 64)) * DIM + h * HD;
        const float* vbase = v + ((size_t)(b * SEQL + nt * 64)) * DIM + h * HD;
        __syncthreads();
#pragma unroll
        for (int it = 0; it < 4; it++) {
            int lin = tid + it * 256;
            int r = lin >> 4;
            int d = (lin & 15) * 4;
            float4 kv = *(const float4*)(kbase + (size_t)r * DIM + d);
            KsT[(d + 0) * APAD + r] = kv.x;
            KsT[(d + 1) * APAD + r] = kv.y;
            KsT[(d + 2) * APAD + r] = kv.z;
            KsT[(d + 3) * APAD + r] = kv.w;
            float4 vv = *(const float4*)(vbase + (size_t)r * DIM + d);
            *(float4*)&Vs[r * APAD + d] = vv;
        }
        __syncthreads();

        float s4[4][4];
#pragma unroll
        for (int i = 0; i < 4; i++)
#pragma unroll
            for (int j = 0; j < 4; j++) s4[i][j] = 0.f;
#pragma unroll 4
        for (int d = 0; d < 64; d++) {
            float4 a = *(const float4*)&QsT[d * APAD + ty * 4];
            float4 bb = *(const float4*)&KsT[d * APAD + tx * 4];
            float af[4] = {a.x, a.y, a.z, a.w};
            float bf[4] = {bb.x, bb.y, bb.z, bb.w};
#pragma unroll
            for (int i = 0; i < 4; i++)
#pragma unroll
                for (int j = 0; j < 4; j++)
                    s4[i][j] = fmaf(af[i], bf[j], s4[i][j]);
        }

#pragma unroll
        for (int i = 0; i < 4; i++) {
            float rm = fmaxf(fmaxf(s4[i][0], s4[i][1]), fmaxf(s4[i][2], s4[i][3]));
#pragma unroll
            for (int off = 8; off; off >>= 1)
                rm = fmaxf(rm, __shfl_xor_sync(0xffffffffu, rm, off));
            float mn = fmaxf(mi[i], rm);
            float al = __expf(mi[i] - mn);
            mi[i] = mn;
            li[i] *= al;
#pragma unroll
            for (int j = 0; j < 4; j++) accO[i][j] *= al;
            float rs = 0.f;
#pragma unroll
            for (int j = 0; j < 4; j++) {
                s4[i][j] = __expf(s4[i][j] - mn);
                rs += s4[i][j];
            }
#pragma unroll
            for (int off = 8; off; off >>= 1)
                rs += __shfl_xor_sync(0xffffffffu, rs, off);
            li[i] += rs;
#pragma unroll
            for (int j = 0; j < 4; j++)
                Pt[(tx * 4 + j) * APAD + ty * 4 + i] = s4[i][j];
        }
        __syncthreads();

#pragma unroll 4
        for (int n = 0; n < 64; n++) {
            float4 a = *(const float4*)&Pt[n * APAD + ty * 4];
            float4 bb = *(const float4*)&Vs[n * APAD + tx * 4];
            float af[4] = {a.x, a.y, a.z, a.w};
            float bf[4] = {bb.x, bb.y, bb.z, bb.w};
#pragma unroll
            for (int i = 0; i < 4; i++)
#pragma unroll
                for (int j = 0; j < 4; j++)
                    accO[i][j] = fmaf(af[i], bf[j], accO[i][j]);
        }
    }

    float* obase = o + ((size_t)(b * SEQL + m0)) * DIM + h * HD;
#pragma unroll
    for (int i = 0; i < 4; i++) {
        float inv = 1.f / li[i];
#pragma unroll
        for (int j = 0; j < 4; j++)
            obase[(size_t)(ty * 4 + i) * DIM + tx * 4 + j] = accO[i][j] * inv;
    }
}

// ---------------------------------------------------------------------------
// host launcher
// ---------------------------------------------------------------------------
extern "C" void kernel_launch(void* const* d_in, const int* in_sizes, int n_in,
                              void* d_out, int out_size)
{
    const float* x     = (const float*)d_in[0];
    const float* cosT  = (const float*)d_in[3];
    const float* sinT  = (const float*)d_in[4];
    const float* c     = (const float*)d_in[6];
    const float* ln1_w = (const float*)d_in[7];
    const float* Wq    = (const float*)d_in[8];
    const float* Wk    = (const float*)d_in[9];
    const float* Wv    = (const float*)d_in[10];
    const float* Wo    = (const float*)d_in[11];
    const float* ln2_w = (const float*)d_in[12];
    const float* W1    = (const float*)d_in[13];
    const float* b1    = (const float*)d_in[14];
    const float* W2    = (const float*)d_in[15];
    const float* b2    = (const float*)d_in[16];
    const float* ada_w = (const float*)d_in[17];
    const float* ada_b = (const float*)d_in[18];
    float* out = (float*)d_out;

    static float *p_ada = nullptr, *p_h, *p_q, *p_k, *p_v, *p_attn, *p_mid;
    static bool attr_set = false;
    if (!p_ada) {
        cudaGetSymbolAddress((void**)&p_ada,  g_ada);
        cudaGetSymbolAddress((void**)&p_h,    g_h);
        cudaGetSymbolAddress((void**)&p_q,    g_q);
        cudaGetSymbolAddress((void**)&p_k,    g_k);
        cudaGetSymbolAddress((void**)&p_v,    g_v);
        cudaGetSymbolAddress((void**)&p_attn, g_attn);
        cudaGetSymbolAddress((void**)&p_mid,  g_mid);
    }

    // 1) adaLN projection
    ada_kernel<<<ADA_N / 128, 128>>>(c, ada_w, ada_b, p_ada);

    // 2) LN1 + modulate (sh_msa @0, sc_msa @1024)
    ln_mod_kernel<<<T_TOK, 256>>>(x, ln1_w, p_ada, 0, 1024, p_h);

    // 3) QKV projections (tf32 TC)
    dim3 g1(DIM / 128, T_TOK / 128);
    gemm_tc_kernel<EPI_STORE><<<g1, 256>>>(p_h, Wq, p_q, T_TOK, DIM, DIM, nullptr, nullptr, nullptr, 0);
    gemm_tc_kernel<EPI_STORE><<<g1, 256>>>(p_h, Wk, p_k, T_TOK, DIM, DIM, nullptr, nullptr, nullptr, 0);
    gemm_tc_kernel<EPI_STORE><<<g1, 256>>>(p_h, Wv, p_v, T_TOK, DIM, DIM, nullptr, nullptr, nullptr, 0);

    // 4) RoPE
    rope_kernel<<<(T_TOK * NH * 32 + 255) / 256, 256>>>(p_q, p_k, cosT, sinT);

    // 5) attention
    int smem_bytes = 4 * 64 * APAD * sizeof(float); // 69632
    if (!attr_set) {
        cudaFuncSetAttribute(attn_kernel, cudaFuncAttributeMaxDynamicSharedMemorySize, smem_bytes);
        attr_set = true;
    }
    attn_kernel<<<dim3(SEQL / 64, NSEQ * NH), 256, smem_bytes>>>(p_q, p_k, p_v, p_attn);

    // 6) x1 = x + g_msa * (attn @ Wo)  (gate @2048)
    gemm_tc_kernel<EPI_ATTNOUT><<<g1, 256>>>(p_attn, Wo, out, T_TOK, DIM, DIM, nullptr, x, p_ada, 2048);

    // 7) LN2 + modulate (sh_mlp @3072, sc_mlp @4096)
    ln_mod_kernel<<<T_TOK, 256>>>(out, ln2_w, p_ada, 3072, 4096, p_h);

    // 8) mid = gelu(h2 @ W1 + b1)
    dim3 g2(HIDDEN / 128, T_TOK / 128);
    gemm_tc_kernel<EPI_GELU><<<g2, 256>>>(p_h, W1, p_mid, T_TOK, HIDDEN, DIM, b1, nullptr, nullptr, 0);

    // 9) out = x1 + g_mlp * (mid @ W2 + b2)  (gate @5120)
    gemm_tc_kernel<EPI_MLPOUT><<<g1, 256>>>(p_mid, W2, out, T_TOK, DIM, HIDDEN, b2, out, p_ada, 5120);
}